// round 16
// baseline (speedup 1.0000x reference)
#include <cuda_runtime.h>

// ChamferLoss: f[4,8192,3], f_[4,8192,3] -> scalar.
// R16 = R15 (best, 84.5us) with overhead polish only; inner loop untouched:
//  - each thread owns 8 CONSECUTIVE src points -> prologue 6x LDG.128,
//    epilogue 2x STG.128 (was 24/8 scattered 32-bit accesses)
//  - reduceB fused into reduceA via threadfence + atomic counter (one launch
//    saved); counter reset each pass for graph replay; deterministic order.

namespace {
constexpr int kB = 4;
constexpr int kN = 8192;
constexpr int kThreads = 256;
constexpr int kSrcPerThread = 8;
constexpr int kSrcPerBlock = kThreads * kSrcPerThread;  // 2048
constexpr int kChunks = kN / kSrcPerBlock;              // 4
constexpr int kSplits = 8;
constexpr int kDstBlk = kN / kSplits;                   // 1024 = one tile
constexpr int kPairs = kDstBlk / 2;                     // 512 packed pairs
constexpr int kRBlocks = 128;
constexpr float kBig = 3.4e38f;
}  // namespace

// [dir][b][split][n] : s^2 + min_over_split (unclamped)
__device__ float g_rowm[2 * kB * kSplits * kN];
__device__ float g_pblk[kRBlocks];
__device__ unsigned int g_done = 0;

__device__ __forceinline__ unsigned long long pack2(float lo, float hi) {
    unsigned long long r;
    asm("mov.b64 %0, {%1, %2};" : "=l"(r) : "f"(lo), "f"(hi));
    return r;
}
__device__ __forceinline__ void unpack2(unsigned long long v, float& lo, float& hi) {
    asm("mov.b64 {%0, %1}, %2;" : "=f"(lo), "=f"(hi) : "l"(v));
}
__device__ __forceinline__ unsigned long long fma2(unsigned long long a, unsigned long long b,
                                                   unsigned long long c) {
    unsigned long long d;
    asm("fma.rn.f32x2 %0, %1, %2, %3;" : "=l"(d) : "l"(a), "l"(b), "l"(c));
    return d;
}

__global__ void __launch_bounds__(kThreads, 2)
chamfer_dir_kernel(const float* __restrict__ f, const float* __restrict__ f_) {
    // Paired dst tile: sA[jp] = {pack(x0,x1), pack(w0,w1)}   (w = ||p||^2)
    //                  sB[jp] = {pack(y0,y1), pack(z0,z1)}
    __shared__ ulonglong2 sA[kPairs];
    __shared__ ulonglong2 sB[kPairs];

    const int chunk = blockIdx.x;            // 0..3  src chunk
    const int q = blockIdx.y;                // 0..7  dst split
    const int bd = blockIdx.z;               // 0..7  = b*2 + dir
    const int b = bd >> 1;
    const int dir = bd & 1;

    const float* src = (dir == 0) ? f : f_;
    const float* dst = (dir == 0) ? f_ : f;
    src += (size_t)b * kN * 3;
    dst += (size_t)b * kN * 3;

    const int tid = threadIdx.x;
    const int n0 = chunk * kSrcPerBlock + tid * kSrcPerThread;  // 8 consecutive

    // Vectorized prologue: 8 consecutive points = 24 floats = 6 float4.
    float buf[24];
    {
        const float4* p = reinterpret_cast<const float4*>(src + (size_t)n0 * 3);
#pragma unroll
        for (int k = 0; k < 6; ++k) {
            const float4 v = p[k];
            buf[k * 4 + 0] = v.x;
            buf[k * 4 + 1] = v.y;
            buf[k * 4 + 2] = v.z;
            buf[k * 4 + 3] = v.w;
        }
    }

    // Src packs with -2 folded in (free: done once per thread).
    unsigned long long sxx[kSrcPerThread], syy[kSrcPerThread], szz[kSrcPerThread];
    float s2[kSrcPerThread];
    float m0[kSrcPerThread], m1[kSrcPerThread];
#pragma unroll
    for (int i = 0; i < kSrcPerThread; ++i) {
        const float x = buf[3 * i + 0];
        const float y = buf[3 * i + 1];
        const float z = buf[3 * i + 2];
        const float mx = -2.0f * x, my = -2.0f * y, mz = -2.0f * z;
        sxx[i] = pack2(mx, mx);
        syy[i] = pack2(my, my);
        szz[i] = pack2(mz, mz);
        s2[i] = fmaf(z, z, fmaf(y, y, x * x));
        m0[i] = kBig;
        m1[i] = kBig;
    }

    // One tile fill: this block's dst split (512 pairs / 256 threads = 2 iter).
    {
        const float* dt = dst + (size_t)(q * kDstBlk) * 3;
#pragma unroll
        for (int it = 0; it < kPairs / kThreads; ++it) {
            const int jp = it * kThreads + tid;
            const float x0 = dt[jp * 6 + 0];
            const float y0 = dt[jp * 6 + 1];
            const float z0 = dt[jp * 6 + 2];
            const float x1 = dt[jp * 6 + 3];
            const float y1 = dt[jp * 6 + 4];
            const float z1 = dt[jp * 6 + 5];
            const float w0 = fmaf(z0, z0, fmaf(y0, y0, x0 * x0));
            const float w1 = fmaf(z1, z1, fmaf(y1, y1, x1 * x1));
            sA[jp] = make_ulonglong2(pack2(x0, x1), pack2(w0, w1));
            sB[jp] = make_ulonglong2(pack2(y0, y1), pack2(z0, z1));
        }
        __syncthreads();
    }

#pragma unroll 4
    for (int jp = 0; jp < kPairs; ++jp) {
        const ulonglong2 A = sA[jp];  // broadcast LDS.128: x, w
        const ulonglong2 B = sB[jp];  // broadcast LDS.128: y, z
#pragma unroll
        for (int i = 0; i < kSrcPerThread; ++i) {
            unsigned long long c = fma2(A.x, sxx[i], A.y);  // w - 2x*sx  (A only)
            c = fma2(B.x, syy[i], c);                       // .. - 2y*sy
            c = fma2(B.y, szz[i], c);                       // .. - 2z*sz
            float t0, t1;
            unpack2(c, t0, t1);
            m0[i] = fminf(m0[i], t0);
            m1[i] = fminf(m1[i], t1);
        }
    }

    // Vectorized epilogue: 8 consecutive results = 2 float4 STG.
    {
        float v[kSrcPerThread];
#pragma unroll
        for (int i = 0; i < kSrcPerThread; ++i) {
            v[i] = s2[i] + fminf(m0[i], m1[i]);  // UNCLAMPED per-split
        }
        float* outp = &g_rowm[(((size_t)dir * kB + b) * kSplits + q) * kN + n0];
        float4* o4 = reinterpret_cast<float4*>(outp);
        o4[0] = make_float4(v[0], v[1], v[2], v[3]);
        o4[1] = make_float4(v[4], v[5], v[6], v[7]);
    }
}

// Combine splits (min), clamp, per-block partial sum; LAST block (atomic
// counter) does the final deterministic 128-way sum and writes out[0].
__global__ void chamfer_reduce_kernel(float* __restrict__ out) {
    __shared__ float swsum[kThreads / 32];
    __shared__ unsigned int s_last;
    const int k = blockIdx.x;
    const int tid = threadIdx.x;
    const int e = k * kThreads + tid;      // 0..32767 = (b,n)
    const int b = e >> 13;
    const int n = e & (kN - 1);

    float acc = 0.0f;
#pragma unroll
    for (int dir = 0; dir < 2; ++dir) {
        const size_t base = (((size_t)dir * kB + b) * kSplits) * kN + n;
        float v = g_rowm[base];
#pragma unroll
        for (int s = 1; s < kSplits; ++s) {
            v = fminf(v, g_rowm[base + (size_t)s * kN]);
        }
        acc += fmaxf(v, 0.0f);
    }

#pragma unroll
    for (int off = 16; off > 0; off >>= 1) {
        acc += __shfl_xor_sync(0xffffffffu, acc, off);
    }
    if ((tid & 31) == 0) swsum[tid >> 5] = acc;
    __syncthreads();
    if (tid == 0) {
        float t = 0.0f;
#pragma unroll
        for (int w = 0; w < kThreads / 32; ++w) t += swsum[w];
        g_pblk[k] = t;
        __threadfence();
        s_last = (atomicAdd(&g_done, 1u) == (unsigned)(kRBlocks - 1)) ? 1u : 0u;
    }
    __syncthreads();

    if (s_last) {
        // Final deterministic reduction of g_pblk[0..127] by this block.
        float v = (tid < kRBlocks) ? g_pblk[tid] : 0.0f;
#pragma unroll
        for (int off = 16; off > 0; off >>= 1) {
            v += __shfl_xor_sync(0xffffffffu, v, off);
        }
        if ((tid & 31) == 0) swsum[tid >> 5] = v;
        __syncthreads();
        if (tid == 0) {
            float t = 0.0f;
#pragma unroll
            for (int w = 0; w < kThreads / 32; ++w) t += swsum[w];
            out[0] = t / (float)(kN * kB);  // / 32768
            g_done = 0;  // reset for next graph replay
        }
    }
}

extern "C" void kernel_launch(void* const* d_in, const int* in_sizes, int n_in,
                              void* d_out, int out_size) {
    const float* f = (const float*)d_in[0];
    const float* f_ = (const float*)d_in[1];
    (void)in_sizes; (void)n_in; (void)out_size;

    dim3 grid(kChunks, kSplits, kB * 2);   // 4 x 8 x 8 = 256 blocks
    chamfer_dir_kernel<<<grid, kThreads>>>(f, f_);
    chamfer_reduce_kernel<<<kRBlocks, kThreads>>>((float*)d_out);
}

// round 17
// speedup vs baseline: 1.0061x; 1.0061x over previous
#include <cuda_runtime.h>

// ChamferLoss: f[4,8192,3], f_[4,8192,3] -> scalar.
// R17 = R16 with dst split 8 -> 16 (tile 512 dst, 8KB smem): 512 blocks at
// occ 2. Wave 1 = 296 CTAs fills every slot; wave 2 = 216 CTAs is work-stolen
// onto draining SMs, removing the 256-on-296 static imbalance (~13.5%).
// Inner loop / prologue / epilogue / fused reduce byte-identical to R16.

namespace {
constexpr int kB = 4;
constexpr int kN = 8192;
constexpr int kThreads = 256;
constexpr int kSrcPerThread = 8;
constexpr int kSrcPerBlock = kThreads * kSrcPerThread;  // 2048
constexpr int kChunks = kN / kSrcPerBlock;              // 4
constexpr int kSplits = 16;
constexpr int kDstBlk = kN / kSplits;                   // 512 = one tile
constexpr int kPairs = kDstBlk / 2;                     // 256 packed pairs
constexpr int kRBlocks = 128;
constexpr float kBig = 3.4e38f;
}  // namespace

// [dir][b][split][n] : s^2 + min_over_split (unclamped)
__device__ float g_rowm[2 * kB * kSplits * kN];
__device__ float g_pblk[kRBlocks];
__device__ unsigned int g_done = 0;

__device__ __forceinline__ unsigned long long pack2(float lo, float hi) {
    unsigned long long r;
    asm("mov.b64 %0, {%1, %2};" : "=l"(r) : "f"(lo), "f"(hi));
    return r;
}
__device__ __forceinline__ void unpack2(unsigned long long v, float& lo, float& hi) {
    asm("mov.b64 {%0, %1}, %2;" : "=f"(lo), "=f"(hi) : "l"(v));
}
__device__ __forceinline__ unsigned long long fma2(unsigned long long a, unsigned long long b,
                                                   unsigned long long c) {
    unsigned long long d;
    asm("fma.rn.f32x2 %0, %1, %2, %3;" : "=l"(d) : "l"(a), "l"(b), "l"(c));
    return d;
}

__global__ void __launch_bounds__(kThreads, 2)
chamfer_dir_kernel(const float* __restrict__ f, const float* __restrict__ f_) {
    // Paired dst tile: sA[jp] = {pack(x0,x1), pack(w0,w1)}   (w = ||p||^2)
    //                  sB[jp] = {pack(y0,y1), pack(z0,z1)}
    __shared__ ulonglong2 sA[kPairs];
    __shared__ ulonglong2 sB[kPairs];

    const int chunk = blockIdx.x;            // 0..3   src chunk
    const int q = blockIdx.y;                // 0..15  dst split
    const int bd = blockIdx.z;               // 0..7   = b*2 + dir
    const int b = bd >> 1;
    const int dir = bd & 1;

    const float* src = (dir == 0) ? f : f_;
    const float* dst = (dir == 0) ? f_ : f;
    src += (size_t)b * kN * 3;
    dst += (size_t)b * kN * 3;

    const int tid = threadIdx.x;
    const int n0 = chunk * kSrcPerBlock + tid * kSrcPerThread;  // 8 consecutive

    // Vectorized prologue: 8 consecutive points = 24 floats = 6 float4.
    float buf[24];
    {
        const float4* p = reinterpret_cast<const float4*>(src + (size_t)n0 * 3);
#pragma unroll
        for (int k = 0; k < 6; ++k) {
            const float4 v = p[k];
            buf[k * 4 + 0] = v.x;
            buf[k * 4 + 1] = v.y;
            buf[k * 4 + 2] = v.z;
            buf[k * 4 + 3] = v.w;
        }
    }

    // Src packs with -2 folded in (free: done once per thread).
    unsigned long long sxx[kSrcPerThread], syy[kSrcPerThread], szz[kSrcPerThread];
    float s2[kSrcPerThread];
    float m0[kSrcPerThread], m1[kSrcPerThread];
#pragma unroll
    for (int i = 0; i < kSrcPerThread; ++i) {
        const float x = buf[3 * i + 0];
        const float y = buf[3 * i + 1];
        const float z = buf[3 * i + 2];
        const float mx = -2.0f * x, my = -2.0f * y, mz = -2.0f * z;
        sxx[i] = pack2(mx, mx);
        syy[i] = pack2(my, my);
        szz[i] = pack2(mz, mz);
        s2[i] = fmaf(z, z, fmaf(y, y, x * x));
        m0[i] = kBig;
        m1[i] = kBig;
    }

    // One tile fill: 256 pairs / 256 threads = 1 iteration.
    {
        const float* dt = dst + (size_t)(q * kDstBlk) * 3;
        const int jp = tid;
        const float x0 = dt[jp * 6 + 0];
        const float y0 = dt[jp * 6 + 1];
        const float z0 = dt[jp * 6 + 2];
        const float x1 = dt[jp * 6 + 3];
        const float y1 = dt[jp * 6 + 4];
        const float z1 = dt[jp * 6 + 5];
        const float w0 = fmaf(z0, z0, fmaf(y0, y0, x0 * x0));
        const float w1 = fmaf(z1, z1, fmaf(y1, y1, x1 * x1));
        sA[jp] = make_ulonglong2(pack2(x0, x1), pack2(w0, w1));
        sB[jp] = make_ulonglong2(pack2(y0, y1), pack2(z0, z1));
        __syncthreads();
    }

#pragma unroll 4
    for (int jp = 0; jp < kPairs; ++jp) {
        const ulonglong2 A = sA[jp];  // broadcast LDS.128: x, w
        const ulonglong2 B = sB[jp];  // broadcast LDS.128: y, z
#pragma unroll
        for (int i = 0; i < kSrcPerThread; ++i) {
            unsigned long long c = fma2(A.x, sxx[i], A.y);  // w - 2x*sx  (A only)
            c = fma2(B.x, syy[i], c);                       // .. - 2y*sy
            c = fma2(B.y, szz[i], c);                       // .. - 2z*sz
            float t0, t1;
            unpack2(c, t0, t1);
            m0[i] = fminf(m0[i], t0);
            m1[i] = fminf(m1[i], t1);
        }
    }

    // Vectorized epilogue: 8 consecutive results = 2 float4 STG.
    {
        float v[kSrcPerThread];
#pragma unroll
        for (int i = 0; i < kSrcPerThread; ++i) {
            v[i] = s2[i] + fminf(m0[i], m1[i]);  // UNCLAMPED per-split
        }
        float* outp = &g_rowm[(((size_t)dir * kB + b) * kSplits + q) * kN + n0];
        float4* o4 = reinterpret_cast<float4*>(outp);
        o4[0] = make_float4(v[0], v[1], v[2], v[3]);
        o4[1] = make_float4(v[4], v[5], v[6], v[7]);
    }
}

// Combine splits (min), clamp, per-block partial sum; LAST block (atomic
// counter) does the final deterministic 128-way sum and writes out[0].
__global__ void chamfer_reduce_kernel(float* __restrict__ out) {
    __shared__ float swsum[kThreads / 32];
    __shared__ unsigned int s_last;
    const int k = blockIdx.x;
    const int tid = threadIdx.x;
    const int e = k * kThreads + tid;      // 0..32767 = (b,n)
    const int b = e >> 13;
    const int n = e & (kN - 1);

    float acc = 0.0f;
#pragma unroll
    for (int dir = 0; dir < 2; ++dir) {
        const size_t base = (((size_t)dir * kB + b) * kSplits) * kN + n;
        float v = g_rowm[base];
#pragma unroll
        for (int s = 1; s < kSplits; ++s) {
            v = fminf(v, g_rowm[base + (size_t)s * kN]);
        }
        acc += fmaxf(v, 0.0f);
    }

#pragma unroll
    for (int off = 16; off > 0; off >>= 1) {
        acc += __shfl_xor_sync(0xffffffffu, acc, off);
    }
    if ((tid & 31) == 0) swsum[tid >> 5] = acc;
    __syncthreads();
    if (tid == 0) {
        float t = 0.0f;
#pragma unroll
        for (int w = 0; w < kThreads / 32; ++w) t += swsum[w];
        g_pblk[k] = t;
        __threadfence();
        s_last = (atomicAdd(&g_done, 1u) == (unsigned)(kRBlocks - 1)) ? 1u : 0u;
    }
    __syncthreads();

    if (s_last) {
        // Final deterministic reduction of g_pblk[0..127] by this block.
        float v = (tid < kRBlocks) ? g_pblk[tid] : 0.0f;
#pragma unroll
        for (int off = 16; off > 0; off >>= 1) {
            v += __shfl_xor_sync(0xffffffffu, v, off);
        }
        if ((tid & 31) == 0) swsum[tid >> 5] = v;
        __syncthreads();
        if (tid == 0) {
            float t = 0.0f;
#pragma unroll
            for (int w = 0; w < kThreads / 32; ++w) t += swsum[w];
            out[0] = t / (float)(kN * kB);  // / 32768
            g_done = 0;  // reset for next graph replay
        }
    }
}

extern "C" void kernel_launch(void* const* d_in, const int* in_sizes, int n_in,
                              void* d_out, int out_size) {
    const float* f = (const float*)d_in[0];
    const float* f_ = (const float*)d_in[1];
    (void)in_sizes; (void)n_in; (void)out_size;

    dim3 grid(kChunks, kSplits, kB * 2);   // 4 x 16 x 8 = 512 blocks
    chamfer_dir_kernel<<<grid, kThreads>>>(f, f_);
    chamfer_reduce_kernel<<<kRBlocks, kThreads>>>((float*)d_out);
}